// round 2
// baseline (speedup 1.0000x reference)
#include <cuda_runtime.h>
#include <cuda_bf16.h>
#include <cstdint>

#define B   8
#define C   512
#define K   19
#define HW  16384
#define INV_HW (1.0f / 16384.0f)

// tile of pixels handled by one block in kernels 1 and 3
#define TPB 256
#define T   512            // TPB * 2 pixels per block
#define NTILES (HW / T)    // 32

// scratch (allocation-free rule: __device__ globals)
__device__ float g_cf[B * K * C];     // class_feat accumulator
__device__ float g_filt[B * K * C];   // per-sample dynamic filters

__device__ __forceinline__ float sigmoidf_(float z) {
    return 1.0f / (1.0f + __expf(-z));
}

// ---------------------------------------------------------------------------
// Kernel 0: zero the class_feat accumulator (scratch persists across replays)
// ---------------------------------------------------------------------------
__global__ void zero_cf_kernel() {
    int i = blockIdx.x * blockDim.x + threadIdx.x;
    if (i < B * K * C) g_cf[i] = 0.0f;
}

// ---------------------------------------------------------------------------
// Kernel 1: fused mask_conv + sigmoid + masked pooling
//   grid = (NTILES, B), block = TPB
//   dynamic smem: sWm[K*C] (38912 B) + sMask[K*T] (38912 B) = 77824 B
// ---------------------------------------------------------------------------
extern __shared__ float smem1[];

__global__ __launch_bounds__(TPB) void mask_pool_kernel(
    const float* __restrict__ x,
    const float* __restrict__ Wm,
    const float* __restrict__ bm)
{
    float* sWm   = smem1;             // [K][C]
    float* sMask = smem1 + K * C;     // [K][T]

    const int tid = threadIdx.x;
    const int b   = blockIdx.y;
    const int p0  = blockIdx.x * T;
    const float* __restrict__ xb = x + (size_t)b * C * HW;

    // stage Wm into smem
    for (int i = tid; i < K * C; i += TPB) sWm[i] = Wm[i];
    __syncthreads();

    // ---- Phase 1: per-pixel mask (2 pixels per thread) ----
    const int pA = p0 + tid;
    const int pB = pA + TPB;

    float accA[K], accB[K];
#pragma unroll
    for (int k = 0; k < K; k++) {
        float bv = __ldg(&bm[k]);
        accA[k] = bv;
        accB[k] = bv;
    }

#pragma unroll 1
    for (int c = 0; c < C; c += 4) {
        float xa0 = xb[(size_t)(c + 0) * HW + pA];
        float xa1 = xb[(size_t)(c + 1) * HW + pA];
        float xa2 = xb[(size_t)(c + 2) * HW + pA];
        float xa3 = xb[(size_t)(c + 3) * HW + pA];
        float xb0 = xb[(size_t)(c + 0) * HW + pB];
        float xb1 = xb[(size_t)(c + 1) * HW + pB];
        float xb2 = xb[(size_t)(c + 2) * HW + pB];
        float xb3 = xb[(size_t)(c + 3) * HW + pB];
#pragma unroll
        for (int k = 0; k < K; k++) {
            float4 w = *(const float4*)&sWm[k * C + c];
            accA[k] += w.x * xa0 + w.y * xa1 + w.z * xa2 + w.w * xa3;
            accB[k] += w.x * xb0 + w.y * xb1 + w.z * xb2 + w.w * xb3;
        }
    }

#pragma unroll
    for (int k = 0; k < K; k++) {
        sMask[k * T + tid]       = sigmoidf_(accA[k]);
        sMask[k * T + tid + TPB] = sigmoidf_(accB[k]);
    }
    __syncthreads();

    // ---- Phase 2: masked pooling (2 channels per thread) ----
    const int c0 = tid;
    const int c1 = tid + TPB;
    const float* __restrict__ xr0 = xb + (size_t)c0 * HW + p0;
    const float* __restrict__ xr1 = xb + (size_t)c1 * HW + p0;

    float a0[K], a1[K];
#pragma unroll
    for (int k = 0; k < K; k++) { a0[k] = 0.0f; a1[k] = 0.0f; }

#pragma unroll 1
    for (int p = 0; p < T; p += 4) {
        float4 x0 = *(const float4*)(xr0 + p);
        float4 x1 = *(const float4*)(xr1 + p);
#pragma unroll
        for (int k = 0; k < K; k++) {
            float4 m = *(const float4*)&sMask[k * T + p];
            a0[k] += m.x * x0.x + m.y * x0.y + m.z * x0.z + m.w * x0.w;
            a1[k] += m.x * x1.x + m.y * x1.y + m.z * x1.z + m.w * x1.w;
        }
    }

#pragma unroll
    for (int k = 0; k < K; k++) {
        atomicAdd(&g_cf[((size_t)b * K + k) * C + c0], a0[k]);
        atomicAdd(&g_cf[((size_t)b * K + k) * C + c1], a1[k]);
    }
}

// ---------------------------------------------------------------------------
// Kernel 2: filters[b,k,o] = sum_c Wf[k,o,c] * cf[b,k,c]/HW + bf[k,o]
//   grid = (K, 4), block = 128 (o = blockIdx.y*128 + tid); Wf read once.
// ---------------------------------------------------------------------------
__global__ __launch_bounds__(128) void filters_kernel(
    const float* __restrict__ Wf,
    const float* __restrict__ bf)
{
    __shared__ float scf[B * C];   // 16 KB, scaled by 1/HW

    const int k   = blockIdx.x;
    const int tid = threadIdx.x;

    for (int i = tid; i < B * C; i += 128) {
        int bb = i / C, cc = i % C;
        scf[i] = g_cf[((size_t)bb * K + k) * C + cc] * INV_HW;
    }
    __syncthreads();

    const int o = blockIdx.y * 128 + tid;
    const float* __restrict__ wrow = Wf + ((size_t)k * C + o) * C;

    float acc[B];
#pragma unroll
    for (int bb = 0; bb < B; bb++) acc[bb] = 0.0f;

#pragma unroll 1
    for (int c = 0; c < C; c += 4) {
        float4 w = *(const float4*)(wrow + c);
#pragma unroll
        for (int bb = 0; bb < B; bb++) {
            float4 f = *(const float4*)&scf[bb * C + c];
            acc[bb] += w.x * f.x + w.y * f.y + w.z * f.z + w.w * f.w;
        }
    }

    float bias = __ldg(&bf[k * C + o]);
#pragma unroll
    for (int bb = 0; bb < B; bb++)
        g_filt[((size_t)bb * K + k) * C + o] = acc[bb] + bias;
}

// ---------------------------------------------------------------------------
// Kernel 3: pred[b,k,p] = sum_c filters[b,k,c] * x[b,c,p]
//   grid = (NTILES, B), block = TPB; static smem 38912 B
// ---------------------------------------------------------------------------
__global__ __launch_bounds__(TPB) void pred_kernel(
    const float* __restrict__ x,
    float* __restrict__ out)
{
    __shared__ float sF[K * C];

    const int tid = threadIdx.x;
    const int b   = blockIdx.y;
    const int p0  = blockIdx.x * T;
    const float* __restrict__ xb = x + (size_t)b * C * HW;

    for (int i = tid; i < K * C; i += TPB) sF[i] = g_filt[(size_t)b * K * C + i];
    __syncthreads();

    const int pA = p0 + tid;
    const int pB = pA + TPB;

    float accA[K], accB[K];
#pragma unroll
    for (int k = 0; k < K; k++) { accA[k] = 0.0f; accB[k] = 0.0f; }

#pragma unroll 1
    for (int c = 0; c < C; c += 4) {
        float xa0 = xb[(size_t)(c + 0) * HW + pA];
        float xa1 = xb[(size_t)(c + 1) * HW + pA];
        float xa2 = xb[(size_t)(c + 2) * HW + pA];
        float xa3 = xb[(size_t)(c + 3) * HW + pA];
        float xb0 = xb[(size_t)(c + 0) * HW + pB];
        float xb1 = xb[(size_t)(c + 1) * HW + pB];
        float xb2 = xb[(size_t)(c + 2) * HW + pB];
        float xb3 = xb[(size_t)(c + 3) * HW + pB];
#pragma unroll
        for (int k = 0; k < K; k++) {
            float4 w = *(const float4*)&sF[k * C + c];
            accA[k] += w.x * xa0 + w.y * xa1 + w.z * xa2 + w.w * xa3;
            accB[k] += w.x * xb0 + w.y * xb1 + w.z * xb2 + w.w * xb3;
        }
    }

#pragma unroll
    for (int k = 0; k < K; k++) {
        out[((size_t)b * K + k) * HW + pA] = accA[k];
        out[((size_t)b * K + k) * HW + pB] = accB[k];
    }
}

// ---------------------------------------------------------------------------
extern "C" void kernel_launch(void* const* d_in, const int* in_sizes, int n_in,
                              void* d_out, int out_size)
{
    const float* x  = (const float*)d_in[0];
    const float* Wm = (const float*)d_in[1];
    const float* bm = (const float*)d_in[2];
    const float* Wf = (const float*)d_in[3];
    const float* bf = (const float*)d_in[4];
    float* out = (float*)d_out;

    const int smem1 = (K * C + K * T) * sizeof(float);  // 77824 B
    cudaFuncSetAttribute(mask_pool_kernel,
                         cudaFuncAttributeMaxDynamicSharedMemorySize, smem1);

    zero_cf_kernel<<<(B * K * C + 255) / 256, 256>>>();
    mask_pool_kernel<<<dim3(NTILES, B), TPB, smem1>>>(x, Wm, bm);
    filters_kernel<<<dim3(K, 4), 128>>>(Wf, bf);
    pred_kernel<<<dim3(NTILES, B), TPB>>>(x, out);
}